// round 5
// baseline (speedup 1.0000x reference)
#include <cuda_runtime.h>
#include <cstdint>

#define NPOS   1296
#define NPOSX  36
#define BCN    32
#define HW     160
#define SLOT   52                       // floats per (pos,n) record: 49 den + coord + pad (16B aligned)
#define STEPS  (NPOS*10)                // 12960 sequential updates per plane
#define CHUNK  8
#define NCHUNK (STEPS/CHUNK)            // 1620
#define CHUNK_BYTES (CHUNK*SLOT*4)      // 1664
#define CHUNK_PAD   2048                // padded ring chunk (over-copy, branch-free)
#define ROWSTR 164                      // smem row stride (2-way max bank conflict for 7x7 tiles)
#define PLANE_ELEMS (161*ROWSTR)        // 160 rows + 1 dummy row
#define DUMMY  (160*ROWSTR)
#define SMEM_C_BYTES ((2*PLANE_ELEMS + 4*(CHUNK_PAD/4))*4)   // 219,424 B

__device__ float g_den[(size_t)BCN*NPOS*10*SLOT + 1024];   // ~86 MB scratch (den + packed coords)
__device__ float g_M[49*49];
__device__ float g_b2[10*49];

// ---------------- Kernel P: fuse the two linear layers ----------------
__global__ void __launch_bounds__(512) kprep(const float* __restrict__ Wp, const float* __restrict__ bp,
                      const float* __restrict__ pe, const float* __restrict__ Wb,
                      const float* __restrict__ bb) {
    int t = threadIdx.x;
    for (int idx = t; idx < 49*49; idx += blockDim.x) {
        int k = idx/49, j = idx%49;
        float a = 0.f;
        for (int e = 0; e < 128; e++) a = fmaf(Wp[k*128+e], Wb[e*49+j], a);
        g_M[idx] = a;
    }
    for (int idx = t; idx < 10*49; idx += blockDim.x) {
        int n = idx/49, j = idx%49;
        float a = bb[j];
        for (int e = 0; e < 128; e++) a = fmaf(bp[e] + pe[n*128+e], Wb[e*49+j], a);
        g_b2[idx] = a;
    }
}

// ---------------- Kernel A: sim + exact top-10 + fused projection ----------------
__global__ void __launch_bounds__(512) kmain(const float* __restrict__ images) {
    __shared__ float win[400];
    __shared__ float ref[49];
    __shared__ float Ms[49*49];
    __shared__ float b2s[10*49];
    __shared__ unsigned long long red[16];
    __shared__ unsigned widx[10];

    int t  = threadIdx.x;
    int blk = blockIdx.x;
    int p  = blk >> 5;          // position index (x-outer, y-inner)
    int bc = blk & 31;
    int xidx = p / NPOSX, yidx = p % NPOSX;
    int x = 4*xidx, y = 4*yidx;
    int xb0 = max(x-7, 0), yb0 = max(y-7, 0);
    int jmax = (x + 13 - xb0) - 7;     // col-offset validity (winW - P)
    int imax = (y + 13 - yb0) - 7;     // row-offset validity (winH - P)

    const float* ip = images + (size_t)bc*HW*HW;
    for (int idx = t; idx < 400; idx += 512)
        win[idx] = ip[(yb0 + idx/20)*HW + xb0 + idx%20];
    if (t < 49)  ref[t] = ip[(y + t/7)*HW + x + t%7];
    for (int idx = t; idx < 49*49; idx += 512) Ms[idx] = g_M[idx];
    if (t < 490) b2s[t] = g_b2[t];
    __syncthreads();

    // sim[i][j], i=row offset (y-dir), j=col offset (x-dir); pack for exact top-k order
    unsigned long long key = 0ull;
    if (t < 196) {
        int i = t/14, j = t%14;
        if (i <= imax && j <= jmax) {
            float s = 0.f;
            #pragma unroll
            for (int u = 0; u < 7; u++)
                #pragma unroll
                for (int v = 0; v < 7; v++)
                    s = fmaf(win[(i+u)*20 + j+v], ref[u*7+v], s);
            unsigned b   = __float_as_uint(s);
            unsigned ord = (b & 0x80000000u) ? ~b : (b | 0x80000000u);
            key = ((unsigned long long)ord << 32) | (unsigned)(1023 - t);  // ties -> smaller index
        }
    }
    int lane = t & 31, wid = t >> 5;
    for (int r = 0; r < 10; r++) {
        unsigned long long k = key;
        #pragma unroll
        for (int off = 16; off; off >>= 1) {
            unsigned long long o = __shfl_down_sync(0xFFFFFFFFu, k, off);
            if (o > k) k = o;
        }
        if (lane == 0) red[wid] = k;
        __syncthreads();
        if (t == 0) {
            unsigned long long m = red[0];
            for (int w = 1; w < 16; w++) if (red[w] > m) m = red[w];
            widx[r] = 1023u - (unsigned)(m & 0xFFFFFFFFull);
        }
        __syncthreads();
        if (t == (int)widx[r]) key = 0ull;
    }

    // deposits: den[n][j] = bias2[n][j] + sum_k patch[k]*M[k][j],
    // patch[k] = win[oy + k%7][ox + k/7]  (transposed extract)
    size_t base0 = (((size_t)bc*NPOS + p)*10)*SLOT;
    if (t < 490) {
        int n = t/49, j = t%49;
        unsigned w = widx[n];
        int oy = w/14, ox = w%14;
        float acc = b2s[n*49 + j];
        #pragma unroll
        for (int kc = 0; kc < 7; kc++)
            #pragma unroll
            for (int kr = 0; kr < 7; kr++)
                acc = fmaf(win[(oy+kr)*20 + ox+kc], Ms[(kc*7+kr)*49 + j], acc);
        g_den[base0 + n*SLOT + j] = acc;
    }
    if (t < 10) {
        unsigned w = widx[t];
        int oy = w/14, ox = w%14;
        unsigned xi = (unsigned)(oy + xb0);   // source's coordinate swap kept
        unsigned yi = (unsigned)(ox + yb0);
        ((unsigned*)g_den)[base0 + t*SLOT + 49] = xi | (yi << 8);
    }
}

// ---------------- Kernel C: sequential scatter, plane in smem ----------------
__device__ __forceinline__ void cp16(unsigned saddr, const void* g) {
    asm volatile("cp.async.cg.shared.global [%0], [%1], 16;\n" :: "r"(saddr), "l"(g) : "memory");
}
__device__ __forceinline__ void cpcommit() { asm volatile("cp.async.commit_group;\n" ::: "memory"); }
__device__ __forceinline__ void cpwait3()  { asm volatile("cp.async.wait_group 3;\n" ::: "memory"); }

__global__ void __launch_bounds__(32) kscatter(const float* __restrict__ images,
                                               float* __restrict__ out) {
    extern __shared__ float sm[];
    float* img  = sm;
    float* cnt  = sm + PLANE_ELEMS;
    float* ring = sm + 2*PLANE_ELEMS;
    volatile float* vimg = img;
    volatile float* vcnt = cnt;

    int plane = blockIdx.x;
    int lane  = threadIdx.x;
    const float* denp = g_den + (size_t)plane * (STEPS*SLOT);
    unsigned ring_s = (unsigned)__cvta_generic_to_shared(ring);

    // prologue prefetch (3 chunks) overlapped with plane init
    #pragma unroll
    for (int c = 0; c < 3; c++) {
        #pragma unroll
        for (int i = 0; i < 4; i++)
            cp16(ring_s + (unsigned)((c & 3)*CHUNK_PAD + lane*16 + i*512),
                 (const char*)denp + (size_t)c*CHUNK_BYTES + lane*16 + i*512);
        cpcommit();
    }

    const float* src = images + (size_t)plane*HW*HW;
    for (int i = lane; i < HW*HW; i += 32) {
        int r = i/HW, c = i%HW;
        img[r*ROWSTR + c] = src[i];
        cnt[r*ROWSTR + c] = 1.0f;
    }
    img[DUMMY + lane] = 0.f;           // per-lane dummy cells for inactive 2nd element
    cnt[DUMMY + lane] = 1.0f;
    __syncwarp();

    int k1   = lane;
    int off1 = (k1/7)*ROWSTR + (k1%7);
    int k2   = lane + 32;
    bool real2 = (k2 < 49);
    int off2r = real2 ? (k2/7)*ROWSTR + (k2%7) : 0;

    for (int c = 0; c < NCHUNK; c++) {
        if (c + 3 < NCHUNK) {                        // uniform branch
            #pragma unroll
            for (int i = 0; i < 4; i++)
                cp16(ring_s + (unsigned)(((c+3) & 3)*CHUNK_PAD + lane*16 + i*512),
                     (const char*)denp + (size_t)(c+3)*CHUNK_BYTES + lane*16 + i*512);
        }
        cpcommit();
        cpwait3();
        __syncwarp();

        const float*    cb  = ring + (c & 3)*(CHUNK_PAD/4);
        const unsigned* ucb = (const unsigned*)cb;
        unsigned coords[CHUNK]; float dd1[CHUNK], dd2[CHUNK];
        #pragma unroll
        for (int ss = 0; ss < CHUNK; ss++) {         // hoist ring reads off the chain
            coords[ss] = ucb[ss*SLOT + 49];
            dd1[ss]    = cb[ss*SLOT + k1];
            dd2[ss]    = cb[ss*SLOT + k2];           // <=427 < 512: stays in padded chunk
        }
        #pragma unroll
        for (int ss = 0; ss < CHUNK; ss++) {
            unsigned co = coords[ss];
            int xi = (int)(co & 0xFFu), yi = (int)((co >> 8) & 0xFFu);
            int bim = yi*ROWSTR + xi;                // im/cnt-read slice at (y_i, x_i)
            int bct = xi*ROWSTR + yi;                // counter-increment slice at (x_i, y_i)
            int o2i = real2 ? off2r : (DUMMY + lane - bim);
            int o2c = real2 ? off2r : (DUMMY + lane - bct);
            // all reads first (same-warp in-order smem => read-before-write within step)
            float c1 = vcnt[bim + off1];
            float v1 = vimg[bim + off1];
            float c2 = vcnt[bim + o2i];
            float v2 = vimg[bim + o2i];
            float t1 = vcnt[bct + off1];
            float t2 = vcnt[bct + o2c];
            float r1 = __fdividef(fmaf(v1, c1, dd1[ss]), c1 + 1.0f);
            float r2 = __fdividef(fmaf(v2, c2, dd2[ss]), c2 + 1.0f);
            vimg[bim + off1] = r1;
            vimg[bim + o2i]  = r2;
            vcnt[bct + off1] = t1 + 1.0f;
            vcnt[bct + o2c]  = t2 + 1.0f;
        }
    }
    __syncwarp();

    float* op = out + (size_t)plane*HW*HW;
    for (int i = lane; i < HW*HW; i += 32) {
        int r = i/HW, cc = i%HW;
        op[i] = img[r*ROWSTR + cc];
    }
}

extern "C" void kernel_launch(void* const* d_in, const int* in_sizes, int n_in,
                              void* d_out, int out_size) {
    const float* images = (const float*)d_in[0];
    const float* Wp     = (const float*)d_in[1];
    const float* bp     = (const float*)d_in[2];
    const float* pe     = (const float*)d_in[3];
    const float* Wb     = (const float*)d_in[4];
    const float* bb     = (const float*)d_in[5];
    float* out = (float*)d_out;

    cudaFuncSetAttribute(kscatter, cudaFuncAttributeMaxDynamicSharedMemorySize, SMEM_C_BYTES);

    kprep<<<1, 512>>>(Wp, bp, pe, Wb, bb);
    kmain<<<NPOS*BCN, 512>>>(images);
    kscatter<<<BCN, 32, SMEM_C_BYTES>>>(images, out);
}

// round 7
// speedup vs baseline: 1.2673x; 1.2673x over previous
#include <cuda_runtime.h>
#include <cstdint>

#define NPOS   1296
#define NPOSX  36
#define BCN    32
#define HW     160
#define SLOT   52                       // floats per (pos,n) record: 49 den + coord + pad (16B aligned)
#define STEPS  (NPOS*10)                // 12960 sequential updates per plane
#define CHUNK  8
#define NCHUNK (STEPS/CHUNK)            // 1620
#define CHUNK_BYTES (CHUNK*SLOT*4)      // 1664
#define CHUNK_PAD   2048                // padded ring chunk (over-copy, branch-free)
#define ROWSTR 164                      // smem row stride (2-way max bank conflict for 7x7 tiles)
#define PLANE_ELEMS (161*ROWSTR)        // 160 rows + 1 dummy row
#define DUMMY  (160*ROWSTR)
#define SMEM_C_BYTES ((2*PLANE_ELEMS + 4*(CHUNK_PAD/4))*4)   // 219,424 B

__device__ float g_den[(size_t)BCN*NPOS*10*SLOT + 1024];   // ~86 MB scratch (den + packed coords)
__device__ float g_M[49*49];
__device__ float g_b2[10*49];

// ---------------- Kernel P: fuse the two linear layers ----------------
__global__ void __launch_bounds__(256) kprep(const float* __restrict__ Wp, const float* __restrict__ bp,
                      const float* __restrict__ pe, const float* __restrict__ Wb,
                      const float* __restrict__ bb) {
    int t = blockIdx.x * blockDim.x + threadIdx.x;
    int stride = gridDim.x * blockDim.x;
    for (int idx = t; idx < 49*49; idx += stride) {
        int k = idx/49, j = idx%49;
        float a = 0.f;
        for (int e = 0; e < 128; e++) a = fmaf(Wp[k*128+e], Wb[e*49+j], a);
        g_M[idx] = a;
    }
    for (int idx = t; idx < 10*49; idx += stride) {
        int n = idx/49, j = idx%49;
        float a = bb[j];
        for (int e = 0; e < 128; e++) a = fmaf(bp[e] + pe[n*128+e], Wb[e*49+j], a);
        g_b2[idx] = a;
    }
}

// ---------------- Kernel A: sim + exact top-10 + fused projection ----------------
// 256 threads; single-warp top-k; Ms load overlapped with top-k.
__global__ void __launch_bounds__(256, 6) kmain(const float* __restrict__ images) {
    __shared__ float win[400];
    __shared__ float ref[49];
    __shared__ float Ms[49*49];
    __shared__ float b2s[10*49];
    __shared__ unsigned long long keys[224];
    __shared__ unsigned widx[10];

    int t   = threadIdx.x;
    int blk = blockIdx.x;
    int p   = blk >> 5;          // position index (x-outer, y-inner)
    int bc  = blk & 31;
    int xidx = p / NPOSX, yidx = p % NPOSX;
    int x = 4*xidx, y = 4*yidx;
    int xb0 = max(x-7, 0), yb0 = max(y-7, 0);
    int jmax = (x + 13 - xb0) - 7;     // col-offset validity (winW - P)
    int imax = (y + 13 - yb0) - 7;     // row-offset validity (winH - P)

    const float* ip = images + (size_t)bc*HW*HW;
    // phase 0: only win + ref needed before sim
    for (int idx = t; idx < 400; idx += 256)
        win[idx] = ip[(yb0 + idx/20)*HW + xb0 + idx%20];
    if (t < 49)  ref[t] = ip[(y + t/7)*HW + x + t%7];
    __syncthreads();

    // sim[i][j], i=row offset (y-dir), j=col offset (x-dir); composite key for exact top-k order
    unsigned long long key = 0ull;
    if (t < 196) {
        int i = t/14, j = t%14;
        if (i <= imax && j <= jmax) {
            float s = 0.f;
            #pragma unroll
            for (int u = 0; u < 7; u++)
                #pragma unroll
                for (int v = 0; v < 7; v++)
                    s = fmaf(win[(i+u)*20 + j+v], ref[u*7+v], s);
            unsigned b   = __float_as_uint(s);
            unsigned ord = (b & 0x80000000u) ? ~b : (b | 0x80000000u);
            key = ((unsigned long long)ord << 32) | (unsigned)(1023 - t);  // ties -> smaller index
        }
    }
    if (t < 224) keys[t] = key;     // t in [196,224) publish 0 (never selected)
    __syncthreads();

    int lane = t & 31, wid = t >> 5;
    if (wid == 0) {
        // single-warp exact top-10 over 224 keys (7 register-resident keys/lane)
        unsigned long long kk[7];
        #pragma unroll
        for (int s = 0; s < 7; s++) kk[s] = keys[lane + 32*s];
        #pragma unroll
        for (int r = 0; r < 10; r++) {
            unsigned long long m = kk[0];
            #pragma unroll
            for (int s = 1; s < 7; s++) if (kk[s] > m) m = kk[s];
            #pragma unroll
            for (int off = 16; off; off >>= 1) {
                unsigned long long o = __shfl_xor_sync(0xFFFFFFFFu, m, off);
                if (o > m) m = o;
            }
            if (lane == 0) widx[r] = 1023u - (unsigned)(m & 0xFFFFFFFFull);
            #pragma unroll
            for (int s = 0; s < 7; s++) if (kk[s] == m) kk[s] = 0ull;  // index makes keys unique
        }
    } else {
        // warps 1..7 stage Ms and b2s while warp 0 runs top-k
        for (int idx = t - 32; idx < 49*49; idx += 224) Ms[idx] = g_M[idx];
        for (int idx = t - 32; idx < 490;   idx += 224) b2s[idx] = g_b2[idx];
    }
    __syncthreads();

    // deposits: den[n][j] = bias2[n][j] + sum_k patch[k]*M[k][j],
    // patch[k] = win[oy + k%7][ox + k/7]  (transposed extract)
    size_t base0 = (((size_t)bc*NPOS + p)*10)*SLOT;
    #pragma unroll
    for (int base = 0; base < 490; base += 256) {
        int tt = base + t;
        if (tt < 490) {
            int n = tt/49, j = tt%49;
            unsigned w = widx[n];
            int oy = w/14, ox = w%14;
            float acc = b2s[n*49 + j];
            #pragma unroll
            for (int kc = 0; kc < 7; kc++)
                #pragma unroll
                for (int kr = 0; kr < 7; kr++)
                    acc = fmaf(win[(oy+kr)*20 + ox+kc], Ms[(kc*7+kr)*49 + j], acc);
            g_den[base0 + n*SLOT + j] = acc;
        }
    }
    if (t < 10) {
        unsigned w = widx[t];
        int oy = w/14, ox = w%14;
        unsigned xi = (unsigned)(oy + xb0);   // source's coordinate swap kept
        unsigned yi = (unsigned)(ox + yb0);
        ((unsigned*)g_den)[base0 + t*SLOT + 49] = xi | (yi << 8);
    }
}

// ---------------- Kernel C: sequential scatter, plane in smem ----------------
__device__ __forceinline__ void cp16(unsigned saddr, const void* g) {
    asm volatile("cp.async.cg.shared.global [%0], [%1], 16;\n" :: "r"(saddr), "l"(g) : "memory");
}
__device__ __forceinline__ void cpcommit() { asm volatile("cp.async.commit_group;\n" ::: "memory"); }
__device__ __forceinline__ void cpwait3()  { asm volatile("cp.async.wait_group 3;\n" ::: "memory"); }

__global__ void __launch_bounds__(32) kscatter(const float* __restrict__ images,
                                               float* __restrict__ out) {
    extern __shared__ float sm[];
    float* img  = sm;
    float* cnt  = sm + PLANE_ELEMS;
    float* ring = sm + 2*PLANE_ELEMS;
    volatile float* vimg = img;
    volatile float* vcnt = cnt;

    int plane = blockIdx.x;
    int lane  = threadIdx.x;
    const float* denp = g_den + (size_t)plane * (STEPS*SLOT);
    unsigned ring_s = (unsigned)__cvta_generic_to_shared(ring);

    // prologue prefetch (3 chunks) overlapped with plane init
    #pragma unroll
    for (int c = 0; c < 3; c++) {
        #pragma unroll
        for (int i = 0; i < 4; i++)
            cp16(ring_s + (unsigned)((c & 3)*CHUNK_PAD + lane*16 + i*512),
                 (const char*)denp + (size_t)c*CHUNK_BYTES + lane*16 + i*512);
        cpcommit();
    }

    const float* src = images + (size_t)plane*HW*HW;
    for (int i = lane; i < HW*HW; i += 32) {
        int r = i/HW, c = i%HW;
        img[r*ROWSTR + c] = src[i];
        cnt[r*ROWSTR + c] = 1.0f;
    }
    img[DUMMY + lane] = 0.f;           // per-lane dummy cells for inactive 2nd element
    cnt[DUMMY + lane] = 1.0f;
    __syncwarp();

    int k1   = lane;
    int off1 = (k1/7)*ROWSTR + (k1%7);
    int k2   = lane + 32;
    bool real2 = (k2 < 49);
    int off2r = real2 ? (k2/7)*ROWSTR + (k2%7) : 0;

    for (int c = 0; c < NCHUNK; c++) {
        if (c + 3 < NCHUNK) {                        // uniform branch
            #pragma unroll
            for (int i = 0; i < 4; i++)
                cp16(ring_s + (unsigned)(((c+3) & 3)*CHUNK_PAD + lane*16 + i*512),
                     (const char*)denp + (size_t)(c+3)*CHUNK_BYTES + lane*16 + i*512);
        }
        cpcommit();
        cpwait3();
        __syncwarp();

        const float*    cb  = ring + (c & 3)*(CHUNK_PAD/4);
        const unsigned* ucb = (const unsigned*)cb;
        unsigned coords[CHUNK]; float dd1[CHUNK], dd2[CHUNK];
        #pragma unroll
        for (int ss = 0; ss < CHUNK; ss++) {         // hoist ring reads off the chain
            coords[ss] = ucb[ss*SLOT + 49];
            dd1[ss]    = cb[ss*SLOT + k1];
            dd2[ss]    = cb[ss*SLOT + k2];           // <=427 < 512: stays in padded chunk
        }
        #pragma unroll
        for (int ss = 0; ss < CHUNK; ss++) {
            unsigned co = coords[ss];
            int xi = (int)(co & 0xFFu), yi = (int)((co >> 8) & 0xFFu);
            int bim = yi*ROWSTR + xi;                // im/cnt-read slice at (y_i, x_i)
            int bct = xi*ROWSTR + yi;                // counter-increment slice at (x_i, y_i)
            int o2i = real2 ? off2r : (DUMMY + lane - bim);
            int o2c = real2 ? off2r : (DUMMY + lane - bct);
            // all reads first (same-warp in-order smem => read-before-write within step)
            float c1 = vcnt[bim + off1];
            float v1 = vimg[bim + off1];
            float c2 = vcnt[bim + o2i];
            float v2 = vimg[bim + o2i];
            float t1 = vcnt[bct + off1];
            float t2 = vcnt[bct + o2c];
            float r1 = __fdividef(fmaf(v1, c1, dd1[ss]), c1 + 1.0f);
            float r2 = __fdividef(fmaf(v2, c2, dd2[ss]), c2 + 1.0f);
            vimg[bim + off1] = r1;
            vimg[bim + o2i]  = r2;
            vcnt[bct + off1] = t1 + 1.0f;
            vcnt[bct + o2c]  = t2 + 1.0f;
        }
    }
    __syncwarp();

    float* op = out + (size_t)plane*HW*HW;
    for (int i = lane; i < HW*HW; i += 32) {
        int r = i/HW, cc = i%HW;
        op[i] = img[r*ROWSTR + cc];
    }
}

extern "C" void kernel_launch(void* const* d_in, const int* in_sizes, int n_in,
                              void* d_out, int out_size) {
    const float* images = (const float*)d_in[0];
    const float* Wp     = (const float*)d_in[1];
    const float* bp     = (const float*)d_in[2];
    const float* pe     = (const float*)d_in[3];
    const float* Wb     = (const float*)d_in[4];
    const float* bb     = (const float*)d_in[5];
    float* out = (float*)d_out;

    cudaFuncSetAttribute(kscatter, cudaFuncAttributeMaxDynamicSharedMemorySize, SMEM_C_BYTES);

    kprep<<<12, 256>>>(Wp, bp, pe, Wb, bb);
    kmain<<<NPOS*BCN, 256>>>(images);
    kscatter<<<BCN, 32, SMEM_C_BYTES>>>(images, out);
}